// round 2
// baseline (speedup 1.0000x reference)
#include <cuda_runtime.h>
#include <cstdint>

// Problem constants
#define BB    64
#define HH    1024
#define SS    512
#define NTHR  256
#define KK    4           // rows per thread (HH / NTHR)
#define TC    16          // t-steps per staged chunk
#define NCHUNK (SS / TC)  // 32
#define ROWB  80          // padded bytes per row per chunk (64 data + 16 pad) -> LDS conflict N=4
#define STAGE_BYTES (HH * ROWB)            // 81920 per buffer
#define MASK_OFF    (2 * STAGE_BYTES)      // 163840
#define RED_OFF     (MASK_OFF + SS * 4)    // 165888
#define SMEM_TOTAL  (RED_OFF + 2 * 8 * 4 * 4)  // + 2 parities * 8 warps * float4

// Warp-wide sum of three independent values. The three butterfly chains are
// independent, so the SHFL latencies pipeline: critical path = one 5-level tree.
__device__ __forceinline__ void wred3(float& a, float& b, float& c) {
    #pragma unroll
    for (int ofs = 16; ofs > 0; ofs >>= 1) {
        a += __shfl_xor_sync(0xffffffffu, a, ofs);
        b += __shfl_xor_sync(0xffffffffu, b, ofs);
        c += __shfl_xor_sync(0xffffffffu, c, ofs);
    }
}

__device__ __forceinline__ void cp16(uint32_t smem_dst, const void* gmem_src) {
    asm volatile("cp.async.cg.shared.global [%0], [%1], 16;"
                 :: "r"(smem_dst), "l"(gmem_src));
}

__device__ __forceinline__ void stage_chunk(char* smem, const char* seq_b, int chunk, int tid) {
    char* dst_base = smem + (chunk & 1) * STAGE_BYTES;
    const char* src_base = seq_b + (size_t)chunk * (TC * 4);  // 64 B along t
    #pragma unroll
    for (int i = 0; i < 16; i++) {
        int idx = i * NTHR + tid;        // 0..4095 : (row, part)
        int row = idx >> 2;
        int p   = idx & 3;
        uint32_t d = (uint32_t)__cvta_generic_to_shared(dst_base + row * ROWB + p * 16);
        const char* s = src_base + (size_t)row * (SS * 4) + p * 16;
        cp16(d, s);
    }
    asm volatile("cp.async.commit_group;");
}

__global__ void __launch_bounds__(NTHR, 1)
orth_scan_kernel(const float* __restrict__ tree,
                 const float* __restrict__ seq,
                 const float* __restrict__ mask,
                 float* __restrict__ out)
{
    extern __shared__ char sm[];
    const int b    = blockIdx.x;
    const int tid  = threadIdx.x;
    const int wid  = tid >> 5;
    const int lane = tid & 31;

    const char* seq_b = (const char*)(seq + (size_t)b * HH * SS);
    float* msk = (float*)(sm + MASK_OFF);
    float* red = (float*)(sm + RED_OFF);

    // Preload mask row (coalesced, 512 floats)
    #pragma unroll
    for (int i = tid; i < SS; i += NTHR) msk[i] = mask[b * SS + i];

    // Load carried state h (coalesced; thread owns rows tid + k*256)
    float h[KK], scur[KK];
    #pragma unroll
    for (int k = 0; k < KK; k++) h[k] = tree[b * HH + tid + k * NTHR];

    // Stage first two chunks, wait for both (startup only)
    stage_chunk(sm, seq_b, 0, tid);
    stage_chunk(sm, seq_b, 1, tid);
    asm volatile("cp.async.wait_group 0;");
    __syncthreads();

    // Initial partials for t=0
    float pdot = 0.f, phh = 0.f, pss = 0.f;
    #pragma unroll
    for (int k = 0; k < KK; k++) {
        int row = tid + k * NTHR;
        float s0 = *(const float*)(sm + row * ROWB);  // buffer 0, tl=0
        scur[k] = s0;
        pdot = fmaf(h[k], s0, pdot);
        phh  = fmaf(h[k], h[k], phh);
        pss  = fmaf(s0, s0, pss);
    }

    for (int t = 0; t < SS; t++) {
        const int tn = t + 1;
        const bool newchunk = (tn & (TC - 1)) == 0;

        // At a chunk boundary, make sure the next buffer's data has landed.
        if (newchunk && tn < SS) asm volatile("cp.async.wait_group 0;");

        // Warp reduction: three pipelined butterfly chains, one tree of latency.
        wred3(pdot, phh, pss);

        const int par = t & 1;  // double-buffer the reduction slots (race safety)
        if (lane == 0) {
            float4* rp = (float4*)(red + par * 32) + wid;
            *rp = make_float4(pdot, phh, pss, 0.f);
        }
        __syncthreads();

        // Kick off prefetch of chunk c+1 into the now-dead buffer (post-barrier)
        if (newchunk) {
            int c = (tn >> 4) + 1;
            if (c < NCHUNK) stage_chunk(sm, seq_b, c, tid);
        }

        // Cross-warp combine: every thread sums all 8 warp partials (broadcast LDS)
        float dot = 0.f, hh = 0.f, ss = 0.f;
        const float4* rp = (const float4*)(red + par * 32);
        #pragma unroll
        for (int w = 0; w < 8; w++) {
            float4 v = rp[w];
            dot += v.x; hh += v.y; ss += v.z;
        }

        // cos = dot / max(sqrt(hh)*sqrt(ss), 1e-8)  ==  dot * rsqrt(max(hh*ss, 1e-16))
        const float cosv = dot * rsqrtf(fmaxf(hh * ss, 1e-16f));
        const float m = msk[t];

        // Update h with s_t; fuse next-step partials with s_{t+1}.
        const int  buf = (tn >> 4) & 1;
        const int  tl  = tn & (TC - 1);
        const char* sbase = sm + buf * STAGE_BYTES + tl * 4;

        pdot = 0.f; phh = 0.f; pss = 0.f;
        #pragma unroll
        for (int k = 0; k < KK; k++) {
            float sn = *(const float*)(sbase + (tid + k * NTHR) * ROWB);  // s_{t+1} (stale at t=511, unused)
            float u  = fmaf(-cosv, h[k], scur[k]);      // s - h*cos
            float hn = fmaf(u, m, h[k]);                // h + u*m
            hn = fminf(1.0f, fmaxf(-1.0f, hn));         // clip
            pdot = fmaf(hn, sn, pdot);
            phh  = fmaf(hn, hn, phh);
            pss  = fmaf(sn, sn, pss);
            h[k] = hn;
            scur[k] = sn;
        }
    }

    #pragma unroll
    for (int k = 0; k < KK; k++)
        out[b * HH + tid + k * NTHR] = h[k];
}

extern "C" void kernel_launch(void* const* d_in, const int* in_sizes, int n_in,
                              void* d_out, int out_size)
{
    const float* tree = (const float*)d_in[0];  // (B, H)
    const float* seq  = (const float*)d_in[1];  // (B, H, S)
    const float* mask = (const float*)d_in[2];  // (B, S)
    float* out = (float*)d_out;                 // (B, H)

    cudaFuncSetAttribute(orth_scan_kernel,
                         cudaFuncAttributeMaxDynamicSharedMemorySize, SMEM_TOTAL);
    orth_scan_kernel<<<BB, NTHR, SMEM_TOTAL>>>(tree, seq, mask, out);
}

// round 4
// speedup vs baseline: 1.0450x; 1.0450x over previous
#include <cuda_runtime.h>
#include <cstdint>

// Problem constants
#define BB    64
#define HH    1024
#define SS    512
#define NTHR  128
#define NW    4           // warps per CTA (one per SMSP -> no arbiter contention)
#define KK    8           // rows per thread (HH / NTHR)
#define TC    16          // t-steps per staged chunk
#define NCHUNK (SS / TC)  // 32
#define ROWB  80          // padded bytes per row per chunk (64 data + 16 pad)
#define STAGE_BYTES (HH * ROWB)            // 81920 per buffer
#define MASK_OFF    (2 * STAGE_BYTES)      // 163840
#define RED_OFF     (MASK_OFF + SS * 4)    // 165888
#define SMEM_TOTAL  (RED_OFF + 2 * NW * 4 * 4)  // + 2 parities * 4 warps * float4

// Warp-wide sum of three independent values; three butterfly chains pipeline,
// critical path = one 5-level tree.
__device__ __forceinline__ void wred3(float& a, float& b, float& c) {
    #pragma unroll
    for (int ofs = 16; ofs > 0; ofs >>= 1) {
        a += __shfl_xor_sync(0xffffffffu, a, ofs);
        b += __shfl_xor_sync(0xffffffffu, b, ofs);
        c += __shfl_xor_sync(0xffffffffu, c, ofs);
    }
}

__device__ __forceinline__ void cp16(uint32_t smem_dst, const void* gmem_src) {
    asm volatile("cp.async.cg.shared.global [%0], [%1], 16;"
                 :: "r"(smem_dst), "l"(gmem_src));
}

__device__ __forceinline__ void stage_chunk(char* smem, const char* seq_b, int chunk, int tid) {
    char* dst_base = smem + (chunk & 1) * STAGE_BYTES;
    const char* src_base = seq_b + (size_t)chunk * (TC * 4);  // 64 B along t
    #pragma unroll
    for (int i = 0; i < 32; i++) {
        int idx = i * NTHR + tid;        // 0..4095 : (row, part)
        int row = idx >> 2;
        int p   = idx & 3;
        uint32_t d = (uint32_t)__cvta_generic_to_shared(dst_base + row * ROWB + p * 16);
        const char* s = src_base + (size_t)row * (SS * 4) + p * 16;
        cp16(d, s);
    }
    asm volatile("cp.async.commit_group;");
}

__global__ void __launch_bounds__(NTHR, 1)
orth_scan_kernel(const float* __restrict__ tree,
                 const float* __restrict__ seq,
                 const float* __restrict__ mask,
                 float* __restrict__ out)
{
    extern __shared__ char sm[];
    const int b    = blockIdx.x;
    const int tid  = threadIdx.x;
    const int wid  = tid >> 5;
    const int lane = tid & 31;

    const char* seq_b = (const char*)(seq + (size_t)b * HH * SS);
    float* msk = (float*)(sm + MASK_OFF);
    float* red = (float*)(sm + RED_OFF);

    // Preload mask row (coalesced)
    #pragma unroll
    for (int i = tid; i < SS; i += NTHR) msk[i] = mask[b * SS + i];

    // Load carried state h (coalesced; thread owns rows tid + k*128)
    float h[KK], scur[KK];
    #pragma unroll
    for (int k = 0; k < KK; k++) h[k] = tree[b * HH + tid + k * NTHR];

    // Stage first two chunks, wait (startup only)
    stage_chunk(sm, seq_b, 0, tid);
    stage_chunk(sm, seq_b, 1, tid);
    asm volatile("cp.async.wait_group 0;");
    __syncthreads();

    // Initial partials for t=0
    float pdot = 0.f, phh = 0.f, pss = 0.f;
    #pragma unroll
    for (int k = 0; k < KK; k++) {
        int row = tid + k * NTHR;
        float s0 = *(const float*)(sm + row * ROWB);  // buffer 0, tl=0
        scur[k] = s0;
        pdot = fmaf(h[k], s0, pdot);
        phh  = fmaf(h[k], h[k], phh);
        pss  = fmaf(s0, s0, pss);
    }

    for (int t = 0; t < SS; t++) {
        const int tn = t + 1;
        const bool boundary = (tn & (TC - 1)) == 0;
        const int  buf = (tn >> 4) & 1;
        const char* sbase = sm + buf * STAGE_BYTES + (tn & (TC - 1)) * 4;

        float sn[KK];
        float pss_next;

        // Early prefetch of s_{t+1} + its norm partial: independent of cos,
        // so the LDS latency and these FMAs hide under the reduction/barrier.
        // At chunk boundaries the next buffer isn't published yet (needs the
        // barrier for cross-thread cp.async visibility) -> load after barrier.
        if (!boundary) {
            #pragma unroll
            for (int k = 0; k < KK; k++)
                sn[k] = *(const float*)(sbase + (tid + k * NTHR) * ROWB);
            float a0 = 0.f, a1 = 0.f;
            #pragma unroll
            for (int k = 0; k < KK; k += 2) {
                a0 = fmaf(sn[k],     sn[k],     a0);
                a1 = fmaf(sn[k + 1], sn[k + 1], a1);
            }
            pss_next = a0 + a1;
        } else if (tn < SS) {
            asm volatile("cp.async.wait_group 0;");
        }

        // Warp reduction (5-level butterfly, 3 pipelined chains)
        wred3(pdot, phh, pss);

        const int par = t & 1;  // double-buffer reduction slots
        if (lane == 0) {
            float4* rp = (float4*)(red + par * (NW * 4)) + wid;
            *rp = make_float4(pdot, phh, pss, 0.f);
        }
        __syncthreads();

        if (boundary) {
            int c = (tn >> 4) + 1;
            if (c < NCHUNK) stage_chunk(sm, seq_b, c, tid);
            #pragma unroll
            for (int k = 0; k < KK; k++)
                sn[k] = *(const float*)(sbase + (tid + k * NTHR) * ROWB);  // stale at t=511, unused
            float a0 = 0.f, a1 = 0.f;
            #pragma unroll
            for (int k = 0; k < KK; k += 2) {
                a0 = fmaf(sn[k],     sn[k],     a0);
                a1 = fmaf(sn[k + 1], sn[k + 1], a1);
            }
            pss_next = a0 + a1;
        }

        // Cross-warp combine: 4 broadcast LDS.128 + tree adds
        const float4* rp = (const float4*)(red + par * (NW * 4));
        float4 v0 = rp[0], v1 = rp[1], v2 = rp[2], v3 = rp[3];
        float dot = (v0.x + v1.x) + (v2.x + v3.x);
        float hh  = (v0.y + v1.y) + (v2.y + v3.y);
        float ss  = (v0.z + v1.z) + (v2.z + v3.z);

        // cos = dot / max(||h||*||s||, 1e-8) == dot * rsqrt(max(hh*ss, 1e-16))
        const float cosv = dot * rsqrtf(fmaxf(hh * ss, 1e-16f));
        const float m = msk[t];

        // Update h; fuse next-step dot/hh partials (dual accumulators)
        float pd0 = 0.f, pd1 = 0.f, ph0 = 0.f, ph1 = 0.f;
        #pragma unroll
        for (int k = 0; k < KK; k++) {
            float u  = fmaf(-cosv, h[k], scur[k]);      // s - h*cos
            float hn = fmaf(u, m, h[k]);                // h + u*m
            hn = fminf(1.0f, fmaxf(-1.0f, hn));         // clip
            if (k & 1) { pd1 = fmaf(hn, sn[k], pd1); ph1 = fmaf(hn, hn, ph1); }
            else       { pd0 = fmaf(hn, sn[k], pd0); ph0 = fmaf(hn, hn, ph0); }
            h[k] = hn;
            scur[k] = sn[k];
        }
        pdot = pd0 + pd1;
        phh  = ph0 + ph1;
        pss  = pss_next;
    }

    #pragma unroll
    for (int k = 0; k < KK; k++)
        out[b * HH + tid + k * NTHR] = h[k];
}

extern "C" void kernel_launch(void* const* d_in, const int* in_sizes, int n_in,
                              void* d_out, int out_size)
{
    const float* tree = (const float*)d_in[0];  // (B, H)
    const float* seq  = (const float*)d_in[1];  // (B, H, S)
    const float* mask = (const float*)d_in[2];  // (B, S)
    float* out = (float*)d_out;                 // (B, H)

    cudaFuncSetAttribute(orth_scan_kernel,
                         cudaFuncAttributeMaxDynamicSharedMemorySize, SMEM_TOTAL);
    orth_scan_kernel<<<BB, NTHR, SMEM_TOTAL>>>(tree, seq, mask, out);
}

// round 5
// speedup vs baseline: 1.2459x; 1.1923x over previous
#include <cuda_runtime.h>
#include <cstdint>

// Problem constants
#define BB    64
#define HH    1024
#define SS    512
#define NTHR  128
#define NW    4           // warps per CTA (one per SMSP)
#define KK    8           // rows per thread (HH / NTHR)
#define TC    16          // t-steps per staged chunk
#define NCHUNK (SS / TC)  // 32
#define ROWB  80          // padded bytes per row per chunk (64 data + 16 pad)
#define STAGE_BYTES (HH * ROWB)            // 81920 per buffer
#define MASK_OFF    (2 * STAGE_BYTES)      // 163840
#define RED_OFF     (MASK_OFF + SS * 4)    // 165888
#define SMEM_TOTAL  (RED_OFF + 2 * NW * 4 * 4)

// Raw-PTX butterfly shuffle: guaranteed single SHFL, no WARPSYNC envelope.
__device__ __forceinline__ float shfl_bfly(float v, int ofs) {
    unsigned r;
    asm volatile("shfl.sync.bfly.b32 %0, %1, %2, 0x1f, 0xffffffff;"
                 : "=r"(r) : "r"(__float_as_uint(v)), "r"(ofs));
    return __uint_as_float(r);
}

// Three independent 5-level butterfly chains; latencies pipeline.
__device__ __forceinline__ void wred3(float& a, float& b, float& c) {
    #pragma unroll
    for (int ofs = 16; ofs > 0; ofs >>= 1) {
        a += shfl_bfly(a, ofs);
        b += shfl_bfly(b, ofs);
        c += shfl_bfly(c, ofs);
    }
}

__device__ __forceinline__ void cp16(uint32_t smem_dst, const void* gmem_src) {
    asm volatile("cp.async.cg.shared.global [%0], [%1], 16;"
                 :: "r"(smem_dst), "l"(gmem_src));
}

// Stage 4 of the 32 (128-thread) slices of a chunk. piece in [0,8).
__device__ __forceinline__ void stage_piece(char* smem, const char* seq_b,
                                            int chunk, int piece, int tid) {
    char* dst_base = smem + (chunk & 1) * STAGE_BYTES;
    const char* src_base = seq_b + (size_t)chunk * (TC * 4);
    #pragma unroll
    for (int j = 0; j < 4; j++) {
        int idx = (piece * 4 + j) * NTHR + tid;   // (row, part)
        int row = idx >> 2;
        int p   = idx & 3;
        uint32_t d = (uint32_t)__cvta_generic_to_shared(dst_base + row * ROWB + p * 16);
        const char* s = src_base + (size_t)row * (SS * 4) + p * 16;
        cp16(d, s);
    }
    asm volatile("cp.async.commit_group;");
}

__global__ void __launch_bounds__(NTHR, 1)
orth_scan_kernel(const float* __restrict__ tree,
                 const float* __restrict__ seq,
                 const float* __restrict__ mask,
                 float* __restrict__ out)
{
    extern __shared__ char sm[];
    const int b    = blockIdx.x;
    const int tid  = threadIdx.x;
    const int wid  = tid >> 5;
    const int lane = tid & 31;

    const char* seq_b = (const char*)(seq + (size_t)b * HH * SS);
    float* msk = (float*)(sm + MASK_OFF);
    float* red = (float*)(sm + RED_OFF);

    // Preload mask (coalesced)
    #pragma unroll
    for (int i = tid; i < SS; i += NTHR) msk[i] = mask[b * SS + i];

    // Carried state
    float h[KK], scur[KK];
    #pragma unroll
    for (int k = 0; k < KK; k++) h[k] = tree[b * HH + tid + k * NTHR];

    // Prologue: stage chunk 0 fully, wait, init partials for t=0.
    #pragma unroll
    for (int p = 0; p < 8; p++) stage_piece(sm, seq_b, 0, p, tid);
    asm volatile("cp.async.wait_group 0;");
    __syncthreads();

    float pdot, phh, pss;
    {
        float d0 = 0.f, d1 = 0.f, q0 = 0.f, q1 = 0.f, s0a = 0.f, s1a = 0.f;
        #pragma unroll
        for (int k = 0; k < KK; k++) {
            int row = tid + k * NTHR;
            float s0 = *(const float*)(sm + row * ROWB);
            scur[k] = s0;
            if (k & 1) { d1 = fmaf(h[k], s0, d1); q1 = fmaf(h[k], h[k], q1); s1a = fmaf(s0, s0, s1a); }
            else       { d0 = fmaf(h[k], s0, d0); q0 = fmaf(h[k], h[k], q0); s0a = fmaf(s0, s0, s0a); }
        }
        pdot = d0 + d1; phh = q0 + q1; pss = s0a + s1a;
    }

    for (int c = 0; c < NCHUNK; c++) {
        char* bufc = sm + (c & 1) * STAGE_BYTES;
        char* bufn = sm + ((c + 1) & 1) * STAGE_BYTES;
        const bool not_last = (c + 1) < NCHUNK;

        #pragma unroll
        for (int tl = 0; tl < TC; tl++) {
            const int t   = c * TC + tl;
            const int par = tl & 1;                 // 16c even -> parity is compile-time

            // 1. Warp tree first: its 15 SHFLs issue before anything else.
            wred3(pdot, phh, pss);

            // 2. Publish per-warp partials.
            if (lane == 0) {
                float4* rp = (float4*)(red + par * (NW * 4)) + wid;
                *rp = make_float4(pdot, phh, pss, 0.f);
            }

            // 3. Independent work hides under tree/barrier: s_{t+1} + mask.
            float sn[KK];
            const float m = msk[t];
            if (tl < TC - 1) {
                const char* sb = bufc + (tl + 1) * 4;
                #pragma unroll
                for (int k = 0; k < KK; k++)
                    sn[k] = *(const float*)(sb + (tid + k * NTHR) * ROWB);
            } else if (not_last) {
                asm volatile("cp.async.wait_group 0;");   // chunk c+1 fully landed
            }

            __syncthreads();

            // 4. Post-barrier: spread staging of chunk c+1 (4 cp.async/step over
            //    steps 0..7; its target buffer has been dead since chunk start).
            if (tl < 8 && not_last)
                stage_piece(sm, seq_b, c + 1, tl, tid);
            if (tl == TC - 1) {
                // s_{t+1} = first column of next chunk (stale garbage at t=511, unused)
                #pragma unroll
                for (int k = 0; k < KK; k++)
                    sn[k] = *(const float*)(bufn + (tid + k * NTHR) * ROWB);
            }

            // 5. Cross-warp combine (issue loads first, then pss FMAs overlap).
            const float4* rp = (const float4*)(red + par * (NW * 4));
            float4 v0 = rp[0], v1 = rp[1], v2 = rp[2], v3 = rp[3];

            float s0a = 0.f, s1a = 0.f;
            #pragma unroll
            for (int k = 0; k < KK; k += 2) {
                s0a = fmaf(sn[k],     sn[k],     s0a);
                s1a = fmaf(sn[k + 1], sn[k + 1], s1a);
            }

            float dot = (v0.x + v1.x) + (v2.x + v3.x);
            float hh  = (v0.y + v1.y) + (v2.y + v3.y);
            float ss  = (v0.z + v1.z) + (v2.z + v3.z);

            // cos = dot / max(||h||*||s||, 1e-8) == dot * rsqrt(max(hh*ss, 1e-16))
            const float cosv = dot * rsqrtf(fmaxf(hh * ss, 1e-16f));

            // 6. Update + fused next-step partials (4 accumulators each).
            float pd0 = 0.f, pd1 = 0.f, pd2 = 0.f, pd3 = 0.f;
            float ph0 = 0.f, ph1 = 0.f, ph2 = 0.f, ph3 = 0.f;
            #pragma unroll
            for (int k = 0; k < KK; k++) {
                float u  = fmaf(-cosv, h[k], scur[k]);   // s - h*cos
                float hn = fmaf(u, m, h[k]);             // h + u*m
                hn = fminf(1.0f, fmaxf(-1.0f, hn));      // clip
                switch (k & 3) {
                    case 0: pd0 = fmaf(hn, sn[k], pd0); ph0 = fmaf(hn, hn, ph0); break;
                    case 1: pd1 = fmaf(hn, sn[k], pd1); ph1 = fmaf(hn, hn, ph1); break;
                    case 2: pd2 = fmaf(hn, sn[k], pd2); ph2 = fmaf(hn, hn, ph2); break;
                    default: pd3 = fmaf(hn, sn[k], pd3); ph3 = fmaf(hn, hn, ph3); break;
                }
                h[k] = hn;
                scur[k] = sn[k];
            }
            pdot = (pd0 + pd1) + (pd2 + pd3);
            phh  = (ph0 + ph1) + (ph2 + ph3);
            pss  = s0a + s1a;
        }
    }

    #pragma unroll
    for (int k = 0; k < KK; k++)
        out[b * HH + tid + k * NTHR] = h[k];
}

extern "C" void kernel_launch(void* const* d_in, const int* in_sizes, int n_in,
                              void* d_out, int out_size)
{
    const float* tree = (const float*)d_in[0];  // (B, H)
    const float* seq  = (const float*)d_in[1];  // (B, H, S)
    const float* mask = (const float*)d_in[2];  // (B, S)
    float* out = (float*)d_out;                 // (B, H)

    cudaFuncSetAttribute(orth_scan_kernel,
                         cudaFuncAttributeMaxDynamicSharedMemorySize, SMEM_TOTAL);
    orth_scan_kernel<<<BB, NTHR, SMEM_TOTAL>>>(tree, seq, mask, out);
}

// round 6
// speedup vs baseline: 1.3923x; 1.1175x over previous
#include <cuda_runtime.h>
#include <cstdint>

#define BB    64
#define HH    1024
#define SS    512
#define NTHR  128
#define NW    4
#define KK    8           // rows per thread
#define TC    16          // t-steps per staged chunk
#define NCHUNK (SS / TC)  // 32
#define ROWB  80          // 64 B data (16 t-floats) + 16 B pad per row
#define STAGE_BYTES (HH * ROWB)
#define MASK_OFF    (2 * STAGE_BYTES)
#define RED_OFF     (MASK_OFF + SS * 4)
#define SMEM_TOTAL  (RED_OFF + 2 * NW * 4 * 4)

__device__ __forceinline__ float shfl_bfly(float v, int ofs) {
    unsigned r;
    asm volatile("shfl.sync.bfly.b32 %0, %1, %2, 0x1f, 0xffffffff;"
                 : "=r"(r) : "r"(__float_as_uint(v)), "r"(ofs));
    return __uint_as_float(r);
}

__device__ __forceinline__ void wred3(float& a, float& b, float& c) {
    #pragma unroll
    for (int ofs = 16; ofs > 0; ofs >>= 1) {
        a += shfl_bfly(a, ofs);
        b += shfl_bfly(b, ofs);
        c += shfl_bfly(c, ofs);
    }
}

__device__ __forceinline__ void cp16(uint32_t smem_dst, const void* gmem_src) {
    asm volatile("cp.async.cg.shared.global [%0], [%1], 16;"
                 :: "r"(smem_dst), "l"(gmem_src));
}

// Stage 4 of the 32 per-thread 16B slices of a chunk. piece in [0,8).
__device__ __forceinline__ void stage_piece(char* smem, const char* seq_b,
                                            int chunk, int piece, int tid) {
    char* dst_base = smem + (chunk & 1) * STAGE_BYTES;
    const char* src_base = seq_b + (size_t)chunk * (TC * 4);
    #pragma unroll
    for (int j = 0; j < 4; j++) {
        int idx = (piece * 4 + j) * NTHR + tid;
        int row = idx >> 2;
        int p   = idx & 3;
        uint32_t d = (uint32_t)__cvta_generic_to_shared(dst_base + row * ROWB + p * 16);
        const char* s = src_base + (size_t)row * (SS * 4) + p * 16;
        cp16(d, s);
    }
    asm volatile("cp.async.commit_group;");
}

__global__ void __launch_bounds__(NTHR, 1)
orth_scan_kernel(const float* __restrict__ tree,
                 const float* __restrict__ seq,
                 const float* __restrict__ mask,
                 float* __restrict__ out)
{
    extern __shared__ char sm[];
    const int b    = blockIdx.x;
    const int tid  = threadIdx.x;
    const int wid  = tid >> 5;
    const int lane = tid & 31;

    const char* seq_b = (const char*)(seq + (size_t)b * HH * SS);
    float* msk = (float*)(sm + MASK_OFF);
    float* red = (float*)(sm + RED_OFF);

    #pragma unroll
    for (int i = tid; i < SS; i += NTHR) msk[i] = mask[b * SS + i];

    float h[KK], scur[KK];
    #pragma unroll
    for (int k = 0; k < KK; k++) h[k] = tree[b * HH + tid + k * NTHR];

    // Prologue: stage chunk 0, wait, load s-window group 0, init partials.
    #pragma unroll
    for (int p = 0; p < 8; p++) stage_piece(sm, seq_b, 0, p, tid);
    asm volatile("cp.async.wait_group 0;");
    __syncthreads();

    float4 s4[KK];                 // register window: s for 4 consecutive t per row
    const uint32_t rowbase = tid * ROWB;

    float pdot, phh, pss;
    {
        float d0 = 0.f, d1 = 0.f, q0 = 0.f, q1 = 0.f, s0a = 0.f, s1a = 0.f;
        #pragma unroll
        for (int k = 0; k < KK; k++) {
            s4[k] = *(const float4*)(sm + rowbase + k * (NTHR * ROWB));
            float s0 = s4[k].x;
            scur[k] = s0;
            if (k & 1) { d1 = fmaf(h[k], s0, d1); q1 = fmaf(h[k], h[k], q1); s1a = fmaf(s0, s0, s1a); }
            else       { d0 = fmaf(h[k], s0, d0); q0 = fmaf(h[k], h[k], q0); s0a = fmaf(s0, s0, s0a); }
        }
        pdot = d0 + d1; phh = q0 + q1; pss = s0a + s1a;
    }

    for (int c = 0; c < NCHUNK; c++) {
        char* bufc = sm + (c & 1) * STAGE_BYTES;
        char* bufn = sm + ((c + 1) & 1) * STAGE_BYTES;
        const bool not_last = (c + 1) < NCHUNK;

        #pragma unroll
        for (int tl = 0; tl < TC; tl++) {
            const int t    = c * TC + tl;
            const int par  = tl & 1;
            const int comp = (tl + 1) & 3;          // component of s4 holding s_{t+1}

            // 1. Warp tree (15 SHFLs) issues first.
            wred3(pdot, phh, pss);

            // 2. Independent pre-barrier work (hides under tree/barrier):
            //    refill the 4-step s-window from the CURRENT buffer (valid all chunk).
            const float m = msk[t];
            if ((tl & 3) == 3 && tl != TC - 1) {
                const char* gb = bufc + (tl + 1) * 4;
                #pragma unroll
                for (int k = 0; k < KK; k++)
                    s4[k] = *(const float4*)(gb + rowbase + k * (NTHR * ROWB));
            }
            if (tl == TC - 1 && not_last)
                asm volatile("cp.async.wait_group 0;");   // chunk c+1 landed

            // 3. Publish per-warp partials (depends on tree -> issues last).
            if (lane == 0) {
                float4* rp = (float4*)(red + par * (NW * 4)) + wid;
                *rp = make_float4(pdot, phh, pss, 0.f);
            }
            __syncthreads();

            // 4. Post-barrier: chain-critical combine loads FIRST...
            const float4* rp = (const float4*)(red + par * (NW * 4));
            float4 v0 = rp[0], v1 = rp[1], v2 = rp[2], v3 = rp[3];

            // ...then window refill at chunk boundary (next buffer, just published)...
            if (tl == TC - 1) {
                #pragma unroll
                for (int k = 0; k < KK; k++)
                    s4[k] = *(const float4*)(bufn + rowbase + k * (NTHR * ROWB));
                // at t=511 these are stale-but-in-bounds; results discarded
            }
            // ...then the staging burst for chunk c+1 (never ahead of the chain).
            if (tl < 8 && not_last)
                stage_piece(sm, seq_b, c + 1, tl, tid);

            // 5. Extract s_{t+1}; pss partial is h-independent.
            float sn[KK];
            #pragma unroll
            for (int k = 0; k < KK; k++)
                sn[k] = (comp == 0) ? s4[k].x : (comp == 1) ? s4[k].y
                      : (comp == 2) ? s4[k].z : s4[k].w;

            float s0a = 0.f, s1a = 0.f;
            #pragma unroll
            for (int k = 0; k < KK; k += 2) {
                s0a = fmaf(sn[k],     sn[k],     s0a);
                s1a = fmaf(sn[k + 1], sn[k + 1], s1a);
            }

            float dot = (v0.x + v1.x) + (v2.x + v3.x);
            float hh  = (v0.y + v1.y) + (v2.y + v3.y);
            float ss  = (v0.z + v1.z) + (v2.z + v3.z);

            // cos = dot / max(||h||*||s||, 1e-8) == dot * rsqrt(max(hh*ss, 1e-16))
            const float cosv = dot * rsqrtf(fmaxf(hh * ss, 1e-16f));

            // 6. Update + fused next-step partials.
            float pd0 = 0.f, pd1 = 0.f, pd2 = 0.f, pd3 = 0.f;
            float ph0 = 0.f, ph1 = 0.f, ph2 = 0.f, ph3 = 0.f;
            #pragma unroll
            for (int k = 0; k < KK; k++) {
                float u  = fmaf(-cosv, h[k], scur[k]);   // s - h*cos
                float hn = fmaf(u, m, h[k]);             // h + u*m
                hn = fminf(1.0f, fmaxf(-1.0f, hn));      // clip
                switch (k & 3) {
                    case 0: pd0 = fmaf(hn, sn[k], pd0); ph0 = fmaf(hn, hn, ph0); break;
                    case 1: pd1 = fmaf(hn, sn[k], pd1); ph1 = fmaf(hn, hn, ph1); break;
                    case 2: pd2 = fmaf(hn, sn[k], pd2); ph2 = fmaf(hn, hn, ph2); break;
                    default: pd3 = fmaf(hn, sn[k], pd3); ph3 = fmaf(hn, hn, ph3); break;
                }
                h[k] = hn;
                scur[k] = sn[k];
            }
            pdot = (pd0 + pd1) + (pd2 + pd3);
            phh  = (ph0 + ph1) + (ph2 + ph3);
            pss  = s0a + s1a;
        }
    }

    #pragma unroll
    for (int k = 0; k < KK; k++)
        out[b * HH + tid + k * NTHR] = h[k];
}

extern "C" void kernel_launch(void* const* d_in, const int* in_sizes, int n_in,
                              void* d_out, int out_size)
{
    const float* tree = (const float*)d_in[0];  // (B, H)
    const float* seq  = (const float*)d_in[1];  // (B, H, S)
    const float* mask = (const float*)d_in[2];  // (B, S)
    float* out = (float*)d_out;                 // (B, H)

    cudaFuncSetAttribute(orth_scan_kernel,
                         cudaFuncAttributeMaxDynamicSharedMemorySize, SMEM_TOTAL);
    orth_scan_kernel<<<BB, NTHR, SMEM_TOTAL>>>(tree, seq, mask, out);
}